// round 7
// baseline (speedup 1.0000x reference)
#include <cuda_runtime.h>
#include <cstdint>

#define THREADS 256
#define CAP 2048          // candidate buffer capacity (supports k <= CAP)
#define NBINS 256

// Monotone float<->uint key mapping (total order matching IEEE float order)
__device__ __forceinline__ unsigned f2key(float f) {
    unsigned u = __float_as_uint(f);
    return (u & 0x80000000u) ? ~u : (u | 0x80000000u);
}
__device__ __forceinline__ float key2f(unsigned kk) {
    unsigned u = (kk & 0x80000000u) ? (kk ^ 0x80000000u) : ~kk;
    return __uint_as_float(u);
}

// Rare-path append of one float4's hits (as integer keys): one shared atomic per pack.
__device__ __forceinline__ void append_pack(float4 v, float t0, unsigned* s_key, int* s_cnt) {
    int h = (v.x > t0) + (v.y > t0) + (v.z > t0) + (v.w > t0);
    int base = atomicAdd(s_cnt, h);
    int p = base;
    if (v.x > t0) { if (p < CAP) s_key[p] = f2key(v.x); p++; }
    if (v.y > t0) { if (p < CAP) s_key[p] = f2key(v.y); p++; }
    if (v.z > t0) { if (p < CAP) s_key[p] = f2key(v.z); p++; }
    if (v.w > t0) { if (p < CAP) s_key[p] = f2key(v.w); p++; }
}

// Exact ranking of M keys (zero-padded to multiple of 4); writes ranks < k.
// rank_i = #{j<i : kj >= ki} + #{j>i : kj > ki}  == classic stable rank.
// Equal keys are interchangeable floats => output deterministic regardless of
// the (atomic, unordered) insertion order. Requires s_key 16B-aligned.
__device__ __forceinline__ void rank_and_write_keys(const unsigned* __restrict__ s_key,
                                                    int M, int k, float* __restrict__ outr,
                                                    int tid) {
    const int Mpad = (M + 3) & ~3;
    const uint4* __restrict__ k4 = (const uint4*)s_key;
    for (int i = tid; i < M; i += THREADS) {
        const unsigned ki = s_key[i];
        const int ib = i >> 2;
        int rank = 0;
        #pragma unroll 4
        for (int b = 0; b < ib; b++) {
            uint4 v = k4[b];
            rank += (v.x >= ki) + (v.y >= ki) + (v.z >= ki) + (v.w >= ki);
        }
        {
            uint4 v = k4[ib];
            int m = i & 3;
            rank += (0 < m) ? (v.x >= ki) : (v.x > ki);
            rank += (1 < m) ? (v.y >= ki) : (v.y > ki);
            rank += (2 < m) ? (v.z >= ki) : (v.z > ki);
            rank += (3 < m) ? (v.w >= ki) : (v.w > ki);
        }
        #pragma unroll 4
        for (int b = ib + 1; b < (Mpad >> 2); b++) {
            uint4 v = k4[b];
            rank += (v.x > ki) + (v.y > ki) + (v.z > ki) + (v.w > ki);
        }
        if (rank < k) outr[rank] = key2f(ki);
    }
}

__global__ void __launch_bounds__(THREADS)
TopKPooling_20796231647786_kernel(
    const float* __restrict__ x, const int* __restrict__ kp,
    float* __restrict__ out, long long n_x, long long out_n)
{
    __shared__ __align__(16) unsigned s_key[CAP];
    __shared__ __align__(16) unsigned s_key2[CAP];
    __shared__ int s_hist[NBINS];
    __shared__ int s_cnt;
    __shared__ int s_c2;
    __shared__ unsigned s_min, s_max;
    __shared__ unsigned long long s_scale;
    __shared__ int s_bstar;

    const int k = *kp;
    const long long rows = out_n / k;
    const int row_len = (int)(n_x / rows);
    const int tid = threadIdx.x;
    const int lane = tid & 31;
    const float t0 = 2.35f;                  // fast-path pre-filter; fallback keeps it exact

    for (long long r = blockIdx.x; r < rows; r += gridDim.x) {
        const float* __restrict__ xr = x + r * (long long)row_len;
        float* __restrict__ outr = out + r * (long long)k;

        if (tid == 0) s_cnt = 0;
        __syncthreads();

        // ---- Fast path: single streaming pass. Common case per float4:
        // 3x FMNMX + FSETP + skip. Rare case: tiny atomic append block.
        const int nv4 = row_len >> 2;
        const float4* __restrict__ x4 = (const float4*)xr;

        int i = tid;
        for (; i + 3 * THREADS < nv4; i += 4 * THREADS) {
            float4 a = __ldg(&x4[i]);
            float4 b = __ldg(&x4[i + THREADS]);
            float4 c = __ldg(&x4[i + 2 * THREADS]);
            float4 d = __ldg(&x4[i + 3 * THREADS]);
            float ma = fmaxf(fmaxf(a.x, a.y), fmaxf(a.z, a.w));
            float mb = fmaxf(fmaxf(b.x, b.y), fmaxf(b.z, b.w));
            float mc = fmaxf(fmaxf(c.x, c.y), fmaxf(c.z, c.w));
            float md = fmaxf(fmaxf(d.x, d.y), fmaxf(d.z, d.w));
            if (ma > t0) append_pack(a, t0, s_key, &s_cnt);
            if (mb > t0) append_pack(b, t0, s_key, &s_cnt);
            if (mc > t0) append_pack(c, t0, s_key, &s_cnt);
            if (md > t0) append_pack(d, t0, s_key, &s_cnt);
        }
        for (; i < nv4; i += THREADS) {
            float4 a = __ldg(&x4[i]);
            float ma = fmaxf(fmaxf(a.x, a.y), fmaxf(a.z, a.w));
            if (ma > t0) append_pack(a, t0, s_key, &s_cnt);
        }
        for (int j = (nv4 << 2) + tid; j < row_len; j += THREADS) {
            float f = __ldg(&xr[j]);
            if (f > t0) { int s = atomicAdd(&s_cnt, 1); if (s < CAP) s_key[s] = f2key(f); }
        }
        __syncthreads();

        int c = s_cnt;
        if (c >= k && c <= CAP) {
            // ===== Histogram refinement: shrink candidate set from c to m (>=k) =====
            // 1) min/max of candidate keys
            if (tid == 0) { s_min = 0xFFFFFFFFu; s_max = 0u; s_c2 = 0; }
            s_hist[tid] = 0;                 // THREADS == NBINS
            __syncthreads();
            unsigned lmin = 0xFFFFFFFFu, lmax = 0u;
            for (int j = tid; j < c; j += THREADS) {
                unsigned kk = s_key[j];
                lmin = min(lmin, kk); lmax = max(lmax, kk);
            }
            #pragma unroll
            for (int o = 16; o; o >>= 1) {
                lmin = min(lmin, __shfl_down_sync(0xFFFFFFFFu, lmin, o));
                lmax = max(lmax, __shfl_down_sync(0xFFFFFFFFu, lmax, o));
            }
            if (lane == 0) { atomicMin(&s_min, lmin); atomicMax(&s_max, lmax); }
            __syncthreads();
            // 2) monotone binning scale
            if (tid == 0) {
                unsigned long long range = (unsigned long long)(s_max - s_min);
                s_scale = ((unsigned long long)NBINS << 32) / (range + 1ull);
            }
            __syncthreads();
            const unsigned mn = s_min;
            const unsigned long long sc = s_scale;
            // 3) histogram
            for (int j = tid; j < c; j += THREADS) {
                unsigned bin = (unsigned)(((unsigned long long)(s_key[j] - mn) * sc) >> 32);
                atomicAdd(&s_hist[bin], 1);
            }
            __syncthreads();
            // 4) warp 0: suffix scan over 256 bins to find threshold bin b*
            if (tid < 32) {
                int base8 = tid << 3;
                int csum = 0;
                #pragma unroll
                for (int j = 0; j < 8; j++) csum += s_hist[base8 + j];
                int T = csum;                           // suffix-inclusive over chunks
                #pragma unroll
                for (int o = 1; o < 32; o <<= 1) {
                    int v = __shfl_down_sync(0xFFFFFFFFu, T, o);
                    if (tid + o < 32) T += v;
                }
                int Tnext = __shfl_down_sync(0xFFFFFFFFu, T, 1);   // T_{l+1}
                unsigned mask = __ballot_sync(0xFFFFFFFFu, T >= k); // T_0 = c >= k -> nonzero
                int lc = 31 - __clz((int)mask);          // largest chunk with suffix >= k
                if (tid == lc) {
                    int running = (lc == 31) ? 0 : Tnext;
                    int bb = (lc << 3) + 7;
                    for (; bb >= (lc << 3); bb--) {
                        running += s_hist[bb];
                        if (running >= k) break;
                    }
                    s_bstar = bb;
                }
            }
            __syncthreads();
            const int bstar = s_bstar;
            // 5) compact candidates with bin >= b* (strict superset of top-k)
            for (int j = tid; j < c; j += THREADS) {
                unsigned kk = s_key[j];
                unsigned bin = (unsigned)(((unsigned long long)(kk - mn) * sc) >> 32);
                if ((int)bin >= bstar) { int p = atomicAdd(&s_c2, 1); s_key2[p] = kk; }
            }
            __syncthreads();
            int m = s_c2;                    // k <= m <= c <= CAP
            int Mpad = (m + 3) & ~3;
            if (tid < Mpad - m) s_key2[m + tid] = 0;   // pad keys rank below everything
            __syncthreads();
            // 6) exact stable rank among m candidates == global rank
            rank_and_write_keys(s_key2, m, k, outr, tid);
        } else {
            // ---- Exact fallback: bisection for the k-th largest key (never taken on
            // the benchmark distribution; guarantees correctness for any input, k<=CAP)
            long long lo = -1, hi = 0xFFFFFFFFll;
            while (lo + 1 < hi) {
                long long mid = (lo + hi) >> 1;
                unsigned tkey = (unsigned)mid;
                if (tid == 0) s_c2 = 0;
                __syncthreads();
                int local = 0;
                for (int j = tid; j < row_len; j += THREADS)
                    local += (f2key(__ldg(&xr[j])) > tkey) ? 1 : 0;
                #pragma unroll
                for (int o = 16; o; o >>= 1) local += __shfl_down_sync(0xFFFFFFFFu, local, o);
                if (lane == 0) atomicAdd(&s_c2, local);
                __syncthreads();
                int cc = s_c2;
                if (cc < k) hi = mid; else lo = mid;
                __syncthreads();
            }
            unsigned K = (unsigned)hi;               // K = k-th largest key
            if (tid == 0) s_cnt = 0;
            __syncthreads();
            for (int j = tid; j < row_len; j += THREADS) {
                unsigned kf = f2key(__ldg(&xr[j]));
                if (kf > K) { int s = atomicAdd(&s_cnt, 1); if (s < CAP) s_key[s] = kf; }
            }
            __syncthreads();
            int M = s_cnt;                            // M < k <= CAP
            int Mpad = (M + 3) & ~3;
            if (tid < Mpad - M) s_key[M + tid] = 0;
            __syncthreads();
            rank_and_write_keys(s_key, M, k, outr, tid);
            float fk = key2f(K);                      // fill duplicates of the k-th value
            for (int j = M + tid; j < k; j += THREADS) outr[j] = fk;
        }
        __syncthreads();   // protect shared state reuse across row iterations
    }
}

extern "C" void kernel_launch(void* const* d_in, const int* in_sizes, int n_in,
                              void* d_out, int out_size) {
    const float* x = (const float*)d_in[0];
    const int* kp = (const int*)d_in[1];
    long long n_x = (long long)in_sizes[0];
    long long out_n = (long long)out_size;
    int grid = (int)((out_n + 63) / 64);   // one CTA per row when k==64
    if (grid < 1) grid = 1;
    TopKPooling_20796231647786_kernel<<<grid, THREADS>>>(x, kp, (float*)d_out, n_x, out_n);
}